// round 1
// baseline (speedup 1.0000x reference)
#include <cuda_runtime.h>

#define N_NODES 10000
#define N_EDGES 160000
#define HID 256
#define NBOND 6
#define NATOM 62
#define NLAYERS 6

// Scratch (device globals — no allocation allowed)
__device__ float g_x[N_NODES * HID];
__device__ float g_xa[N_NODES * HID];
__device__ float g_xb[N_NODES * HID];
__device__ float g_agg[N_NODES * HID];
__device__ float g_t1[N_NODES * HID];
__device__ float g_h[N_NODES * HID];

// ---------------------------------------------------------------------------
// Embed: x = atom @ embed_w + embed_b   [10000,62]x[62,256]
// ---------------------------------------------------------------------------
#define EMB_NODES 16
__global__ void __launch_bounds__(256) embed_kernel(
    const float* __restrict__ atom, const float* __restrict__ w,
    const float* __restrict__ b)
{
    __shared__ float s_af[EMB_NODES][NATOM];
    int n0 = blockIdx.x * EMB_NODES;
    int tid = threadIdx.x;
    for (int i = tid; i < EMB_NODES * NATOM; i += 256) {
        int r = i / NATOM, c = i % NATOM;
        int n = n0 + r;
        s_af[r][c] = (n < N_NODES) ? atom[(size_t)n * NATOM + c] : 0.f;
    }
    __syncthreads();
    int j = tid;  // output column 0..255
    float acc[EMB_NODES];
    float bj = b[j];
#pragma unroll
    for (int r = 0; r < EMB_NODES; r++) acc[r] = bj;
    for (int k = 0; k < NATOM; k++) {
        float wv = w[k * HID + j];
#pragma unroll
        for (int r = 0; r < EMB_NODES; r++) acc[r] = fmaf(s_af[r][k], wv, acc[r]);
    }
#pragma unroll
    for (int r = 0; r < EMB_NODES; r++) {
        int n = n0 + r;
        if (n < N_NODES) g_x[(size_t)n * HID + j] = acc[r];
    }
}

// ---------------------------------------------------------------------------
// Generic SGEMM: C[M,N] = op(A[M,256] @ W[256,N] (+bias) (+Cprev)), opt ReLU
// BM=128, BN=128, BK=16, 256 threads, 8x8 per-thread microtile (4+4 split).
// ---------------------------------------------------------------------------
template <bool RELU, bool ADDC, bool HASBIAS>
__global__ void __launch_bounds__(256) gemm256(
    const float* __restrict__ A, const float* __restrict__ W,
    const float* __restrict__ bias, const float* __restrict__ Cprev,
    float* __restrict__ C, int M, int N)
{
    __shared__ float As[16][128];  // [k][m]
    __shared__ float Ws[16][128];  // [k][n]
    const int K = 256;
    int col0 = blockIdx.x * 128, row0 = blockIdx.y * 128;
    int tid = threadIdx.x;
    int tx = tid & 15, ty = tid >> 4;

    float acc[8][8];
#pragma unroll
    for (int i = 0; i < 8; i++)
#pragma unroll
        for (int j = 0; j < 8; j++) acc[i][j] = 0.f;

    int ar = tid >> 2;           // 0..63 (+64)
    int ac = (tid & 3) << 2;     // 0,4,8,12
    int wr = tid >> 5;           // 0..7 (+8)
    int wc = (tid & 31) << 2;    // 0..124

    for (int kt = 0; kt < K; kt += 16) {
#pragma unroll
        for (int i = 0; i < 2; i++) {
            int r = ar + i * 64;
            int grow = row0 + r;
            float4 v = make_float4(0.f, 0.f, 0.f, 0.f);
            if (grow < M) v = *(const float4*)(A + (size_t)grow * K + kt + ac);
            As[ac + 0][r] = v.x; As[ac + 1][r] = v.y;
            As[ac + 2][r] = v.z; As[ac + 3][r] = v.w;
        }
#pragma unroll
        for (int i = 0; i < 2; i++) {
            int r = wr + i * 8;
            *(float4*)&Ws[r][wc] =
                *(const float4*)(W + (size_t)(kt + r) * N + col0 + wc);
        }
        __syncthreads();
#pragma unroll
        for (int kk = 0; kk < 16; kk++) {
            float4 a0 = *(const float4*)&As[kk][ty * 4];
            float4 a1 = *(const float4*)&As[kk][64 + ty * 4];
            float4 w0 = *(const float4*)&Ws[kk][tx * 4];
            float4 w1 = *(const float4*)&Ws[kk][64 + tx * 4];
            float af[8] = {a0.x, a0.y, a0.z, a0.w, a1.x, a1.y, a1.z, a1.w};
            float wf[8] = {w0.x, w0.y, w0.z, w0.w, w1.x, w1.y, w1.z, w1.w};
#pragma unroll
            for (int i = 0; i < 8; i++)
#pragma unroll
                for (int j = 0; j < 8; j++)
                    acc[i][j] = fmaf(af[i], wf[j], acc[i][j]);
        }
        __syncthreads();
    }

    int rbase[2] = {row0 + ty * 4, row0 + 64 + ty * 4};
    int cbase[2] = {col0 + tx * 4, col0 + 64 + tx * 4};
#pragma unroll
    for (int ih = 0; ih < 2; ih++)
#pragma unroll
        for (int i = 0; i < 4; i++) {
            int grow = rbase[ih] + i;
            if (grow < M) {
#pragma unroll
                for (int jh = 0; jh < 2; jh++)
#pragma unroll
                    for (int j = 0; j < 4; j++) {
                        int gcol = cbase[jh] + j;
                        float v = acc[ih * 4 + i][jh * 4 + j];
                        if (HASBIAS) v += bias[gcol];
                        if (ADDC) v += Cprev[(size_t)grow * N + gcol];
                        if (RELU) v = fmaxf(v, 0.f);
                        C[(size_t)grow * N + gcol] = v;
                    }
            }
        }
}

// ---------------------------------------------------------------------------
// Fused edge message GEMM + scatter:
//   A[e,:] = relu(xa[src[e]] + xb[dst[e]] + ef[e]@W1c + b1)   (built on the fly)
//   C      = A @ W2 + b2 ; atomicAdd into agg[dst[e]]
// Tile: 128 edges x 128 cols, K=256.
// ---------------------------------------------------------------------------
__global__ void __launch_bounds__(256) edge_msg_gemm(
    const float* __restrict__ xa, const float* __restrict__ xb,
    const int* __restrict__ src, const int* __restrict__ dst,
    const float* __restrict__ ef,
    const float* __restrict__ w1c,  // [6,256]
    const float* __restrict__ b1,   // [256]
    const float* __restrict__ w2,   // [256,256]
    const float* __restrict__ b2,   // [256]
    float* __restrict__ agg)
{
    __shared__ float As[16][128];
    __shared__ float Ws[16][128];
    __shared__ int s_src[128], s_dst[128];
    __shared__ float s_ef[128][NBOND];
    __shared__ float s_w1c[NBOND][256];
    __shared__ float s_b1[256];

    int e0 = blockIdx.y * 128;
    int col0 = blockIdx.x * 128;
    int tid = threadIdx.x;
    int tx = tid & 15, ty = tid >> 4;

    if (tid < 128) {
        s_src[tid] = src[e0 + tid];
        s_dst[tid] = dst[e0 + tid];
    }
    for (int i = tid; i < 128 * NBOND; i += 256)
        s_ef[i / NBOND][i % NBOND] = ef[(size_t)e0 * NBOND + i];
    for (int i = tid; i < NBOND * 256; i += 256)
        s_w1c[i >> 8][i & 255] = w1c[i];
    s_b1[tid] = b1[tid];
    __syncthreads();

    float acc[8][8];
#pragma unroll
    for (int i = 0; i < 8; i++)
#pragma unroll
        for (int j = 0; j < 8; j++) acc[i][j] = 0.f;

    int ar = tid >> 2;
    int ac = (tid & 3) << 2;
    int wr = tid >> 5;
    int wc = (tid & 31) << 2;

    for (int kt = 0; kt < 256; kt += 16) {
#pragma unroll
        for (int i = 0; i < 2; i++) {
            int r = ar + i * 64;
            int k = kt + ac;
            float4 va = *(const float4*)(xa + (size_t)s_src[r] * HID + k);
            float4 vb = *(const float4*)(xb + (size_t)s_dst[r] * HID + k);
            float4 ec = *(const float4*)&s_b1[k];
#pragma unroll
            for (int q = 0; q < NBOND; q++) {
                float e = s_ef[r][q];
                float4 wv = *(const float4*)&s_w1c[q][k];
                ec.x = fmaf(e, wv.x, ec.x);
                ec.y = fmaf(e, wv.y, ec.y);
                ec.z = fmaf(e, wv.z, ec.z);
                ec.w = fmaf(e, wv.w, ec.w);
            }
            As[ac + 0][r] = fmaxf(va.x + vb.x + ec.x, 0.f);
            As[ac + 1][r] = fmaxf(va.y + vb.y + ec.y, 0.f);
            As[ac + 2][r] = fmaxf(va.z + vb.z + ec.z, 0.f);
            As[ac + 3][r] = fmaxf(va.w + vb.w + ec.w, 0.f);
        }
#pragma unroll
        for (int i = 0; i < 2; i++) {
            int r = wr + i * 8;
            *(float4*)&Ws[r][wc] =
                *(const float4*)(w2 + (size_t)(kt + r) * 256 + col0 + wc);
        }
        __syncthreads();
#pragma unroll
        for (int kk = 0; kk < 16; kk++) {
            float4 a0 = *(const float4*)&As[kk][ty * 4];
            float4 a1 = *(const float4*)&As[kk][64 + ty * 4];
            float4 w0 = *(const float4*)&Ws[kk][tx * 4];
            float4 w1 = *(const float4*)&Ws[kk][64 + tx * 4];
            float af[8] = {a0.x, a0.y, a0.z, a0.w, a1.x, a1.y, a1.z, a1.w};
            float wf[8] = {w0.x, w0.y, w0.z, w0.w, w1.x, w1.y, w1.z, w1.w};
#pragma unroll
            for (int i = 0; i < 8; i++)
#pragma unroll
                for (int j = 0; j < 8; j++)
                    acc[i][j] = fmaf(af[i], wf[j], acc[i][j]);
        }
        __syncthreads();
    }

    // epilogue: + b2, scatter-add into agg[dst]
    int rloc[2] = {ty * 4, 64 + ty * 4};
    int cbase[2] = {col0 + tx * 4, col0 + 64 + tx * 4};
    float bv[2][4];
#pragma unroll
    for (int jh = 0; jh < 2; jh++)
#pragma unroll
        for (int j = 0; j < 4; j++) bv[jh][j] = b2[cbase[jh] + j];

#pragma unroll
    for (int ih = 0; ih < 2; ih++)
#pragma unroll
        for (int i = 0; i < 4; i++) {
            int r = rloc[ih] + i;
            float* arow = agg + (size_t)s_dst[r] * HID;
#pragma unroll
            for (int jh = 0; jh < 2; jh++)
#pragma unroll
                for (int j = 0; j < 4; j++) {
                    atomicAdd(arow + cbase[jh] + j,
                              acc[ih * 4 + i][jh * 4 + j] + bv[jh][j]);
                }
        }
}

// ---------------------------------------------------------------------------
// Readout final: out = mean_n( r2[n,:] . w3 + b3 )
// ---------------------------------------------------------------------------
__global__ void __launch_bounds__(256) readout_final(
    const float* __restrict__ r2, const float* __restrict__ w3,
    const float* __restrict__ b3, float* __restrict__ out)
{
    __shared__ float sred[256];
    int n = blockIdx.x * 256 + threadIdx.x;
    float v = 0.f;
    if (n < N_NODES) {
        const float* row = r2 + (size_t)n * 128;
        float s = 0.f;
#pragma unroll
        for (int k = 0; k < 128; k += 4) {
            float4 rv = *(const float4*)(row + k);
            float4 wv = *(const float4*)(w3 + k);
            s += rv.x * wv.x + rv.y * wv.y + rv.z * wv.z + rv.w * wv.w;
        }
        v = (s + b3[0]) * (1.0f / N_NODES);
    }
    sred[threadIdx.x] = v;
    __syncthreads();
    for (int st = 128; st > 0; st >>= 1) {
        if (threadIdx.x < st) sred[threadIdx.x] += sred[threadIdx.x + st];
        __syncthreads();
    }
    if (threadIdx.x == 0) atomicAdd(out, sred[0]);
}

// ---------------------------------------------------------------------------
// Launch
// ---------------------------------------------------------------------------
extern "C" void kernel_launch(void* const* d_in, const int* in_sizes, int n_in,
                              void* d_out, int out_size)
{
    const float* atom = (const float*)d_in[0];
    const int*   eidx = (const int*)d_in[1];
    const float* ef   = (const float*)d_in[2];
    const float* embw = (const float*)d_in[3];
    const float* embb = (const float*)d_in[4];
    const float* mw1  = (const float*)d_in[5];
    const float* mb1  = (const float*)d_in[6];
    const float* mw2  = (const float*)d_in[7];
    const float* mb2  = (const float*)d_in[8];
    const float* uw1  = (const float*)d_in[9];
    const float* ub1  = (const float*)d_in[10];
    const float* uw2  = (const float*)d_in[11];
    const float* ub2  = (const float*)d_in[12];
    const float* rw1  = (const float*)d_in[13];
    const float* rb1  = (const float*)d_in[14];
    const float* rw2  = (const float*)d_in[15];
    const float* rb2  = (const float*)d_in[16];
    const float* rw3  = (const float*)d_in[17];
    const float* rb3  = (const float*)d_in[18];

    const int* src = eidx;
    const int* dst = eidx + N_EDGES;

    float *px, *pxa, *pxb, *pagg, *pt1, *ph;
    cudaGetSymbolAddress((void**)&px,   g_x);
    cudaGetSymbolAddress((void**)&pxa,  g_xa);
    cudaGetSymbolAddress((void**)&pxb,  g_xb);
    cudaGetSymbolAddress((void**)&pagg, g_agg);
    cudaGetSymbolAddress((void**)&pt1,  g_t1);
    cudaGetSymbolAddress((void**)&ph,   g_h);

    embed_kernel<<<(N_NODES + EMB_NODES - 1) / EMB_NODES, 256>>>(atom, embw, embb);

    dim3 gN(2, (N_NODES + 127) / 128);   // 2 x 79
    dim3 gE(2, N_EDGES / 128);           // 2 x 1250

    for (int l = 0; l < NLAYERS; l++) {
        const float* W1 = mw1 + (size_t)l * 518 * HID;   // [518,256] row-major
        const float* U1 = uw1 + (size_t)l * 512 * HID;   // [512,256] row-major

        // xa = x @ W1[0:256], xb = x @ W1[256:512]
        gemm256<false, false, false><<<gN, 256>>>(px, W1, nullptr, nullptr,
                                                  pxa, N_NODES, HID);
        gemm256<false, false, false><<<gN, 256>>>(px, W1 + 256 * HID, nullptr,
                                                  nullptr, pxb, N_NODES, HID);
        cudaMemsetAsync(pagg, 0, sizeof(float) * N_NODES * HID);

        edge_msg_gemm<<<gE, 256>>>(pxa, pxb, src, dst, ef,
                                   W1 + 512 * HID, mb1 + (size_t)l * HID,
                                   mw2 + (size_t)l * HID * HID,
                                   mb2 + (size_t)l * HID, pagg);

        // t1 = x @ U1[0:256]
        gemm256<false, false, false><<<gN, 256>>>(px, U1, nullptr, nullptr,
                                                  pt1, N_NODES, HID);
        // h = relu(agg @ U1[256:512] + ub1 + t1)
        gemm256<true, true, true><<<gN, 256>>>(pagg, U1 + 256 * HID,
                                               ub1 + (size_t)l * HID, pt1,
                                               ph, N_NODES, HID);
        // x = h @ U2 + ub2
        gemm256<false, false, true><<<gN, 256>>>(ph,
                                                 uw2 + (size_t)l * HID * HID,
                                                 ub2 + (size_t)l * HID, nullptr,
                                                 px, N_NODES, HID);
    }

    // readout
    gemm256<true, false, true><<<gN, 256>>>(px, rw1, rb1, nullptr, pt1,
                                            N_NODES, HID);
    dim3 gR(1, (N_NODES + 127) / 128);
    gemm256<true, false, true><<<gR, 256>>>(pt1, rw2, rb2, nullptr, ph,
                                            N_NODES, 128);

    cudaMemsetAsync(d_out, 0, sizeof(float));
    readout_final<<<(N_NODES + 255) / 256, 256>>>(ph, rw3, rb3, (float*)d_out);
}